// round 9
// baseline (speedup 1.0000x reference)
#include <cuda_runtime.h>
#include <cstdint>

// Problem constants (fixed by the reference):
//   B=4, S=4096, D=2048, E=8, T=B*S=16384, C=T/E*1.25=2560, EC=E*C=20480
#define D_DIM    2048
#define T_TOK    16384
#define EC_ROWS  20480
#define EC_PAIRS (EC_ROWS / 2)   // 10240 expert-row pair blocks
#define T_PAIRS  (T_TOK / 2)     // 8192 fallback pair blocks

// Single-launch scatter: blocks [0, EC_PAIRS) each handle 2 expert rows,
// scattering them to their token rows (skipping padding slots where
// scatter_idx == T). Blocks [EC_PAIRS, EC_PAIRS+T_PAIRS) handle 2 tokens
// each, writing the x fallback for dropped tokens. Writer sets are disjoint
// and cover every output row (kept XOR dropped), so one kernel suffices.
// Block shape is the measured-best copy shape: 128 lanes/row, 4 float4/lane.
__global__ __launch_bounds__(256) void moe_scatter_kernel(
    const float* __restrict__ expert_outputs,   // [EC, D]
    const float* __restrict__ x,                // [T, D]
    const float* __restrict__ route_prob_max,   // [T]
    const int*   __restrict__ scatter_idx,      // [EC]
    const unsigned char* __restrict__ dropped,  // [T] bool
    float* __restrict__ out)                    // [T, D]
{
    const int tid  = threadIdx.x;
    const int half = tid >> 7;                  // 0 or 1: which row of the pair
    const int lane = tid & 127;
    const int bid  = blockIdx.x;

    const float4* __restrict__ src4;
    float4* __restrict__ dst4;
    float factor;

    if (bid < EC_PAIRS) {
        const int i = bid * 2 + half;           // expert slot
        const int r = __ldg(scatter_idx + i);   // broadcast within the half
        if (r >= T_TOK) return;                 // padding slot: no traffic
        src4   = reinterpret_cast<const float4*>(expert_outputs + (size_t)i * D_DIM);
        dst4   = reinterpret_cast<float4*>(out + (size_t)r * D_DIM);
        factor = __ldg(route_prob_max + r);     // overlaps the row loads
    } else {
        const int t = (bid - EC_PAIRS) * 2 + half;
        if (!dropped[t]) return;                // covered by the scatter path
        src4   = reinterpret_cast<const float4*>(x + (size_t)t * D_DIM);
        dst4   = reinterpret_cast<float4*>(out + (size_t)t * D_DIM);
        factor = 1.0f;
    }

    float4 v0 = __ldcs(&src4[lane]);
    float4 v1 = __ldcs(&src4[lane + 128]);
    float4 v2 = __ldcs(&src4[lane + 256]);
    float4 v3 = __ldcs(&src4[lane + 384]);

    v0.x *= factor; v0.y *= factor; v0.z *= factor; v0.w *= factor;
    v1.x *= factor; v1.y *= factor; v1.z *= factor; v1.w *= factor;
    v2.x *= factor; v2.y *= factor; v2.z *= factor; v2.w *= factor;
    v3.x *= factor; v3.y *= factor; v3.z *= factor; v3.w *= factor;

    __stcs(&dst4[lane],       v0);
    __stcs(&dst4[lane + 128], v1);
    __stcs(&dst4[lane + 256], v2);
    __stcs(&dst4[lane + 384], v3);
}

extern "C" void kernel_launch(void* const* d_in, const int* in_sizes, int n_in,
                              void* d_out, int out_size) {
    const float*         expert_outputs = (const float*)d_in[0];
    const float*         x              = (const float*)d_in[1];
    const float*         route_prob_max = (const float*)d_in[2];
    const int*           scatter_idx    = (const int*)d_in[3];
    const unsigned char* dropped        = (const unsigned char*)d_in[4];
    float* out = (float*)d_out;

    moe_scatter_kernel<<<EC_PAIRS + T_PAIRS, 256>>>(
        expert_outputs, x, route_prob_max, scatter_idx, dropped, out);
}

// round 10
// speedup vs baseline: 1.0229x; 1.0229x over previous
#include <cuda_runtime.h>
#include <cstdint>

// Problem constants (fixed by the reference):
//   B=4, S=4096, D=2048, E=8, T=B*S=16384, C=T/E*1.25=2560, EC=E*C=20480
#define D_DIM    2048
#define T_TOK    16384
#define EC_ROWS  20480
#define EC_PAIRS (EC_ROWS / 2)   // 10240 blocks, 2 expert slots each
#define T_PAIRS  (T_TOK / 2)     // first 8192 blocks also cover 2 tokens' fallback

// Single-launch scatter with compacted grid: every block handles 2 expert
// slots (skipping padding slots with scatter_idx == T), and the first
// T_PAIRS blocks ALSO handle the x-fallback for 2 tokens (row copied only
// if dropped — rare/never in this data, so the check is ~2 cached byte
// loads). Writer sets are disjoint and cover every output row.
__global__ __launch_bounds__(256) void moe_scatter_kernel(
    const float* __restrict__ expert_outputs,   // [EC, D]
    const float* __restrict__ x,                // [T, D]
    const float* __restrict__ route_prob_max,   // [T]
    const int*   __restrict__ scatter_idx,      // [EC]
    const unsigned char* __restrict__ dropped,  // [T] bool
    float* __restrict__ out)                    // [T, D]
{
    const int tid  = threadIdx.x;
    const int half = tid >> 7;                  // 0 or 1: which row of the pair
    const int lane = tid & 127;
    const int bid  = blockIdx.x;

    // ---- Scatter section: expert slot -> token row ----
    {
        const int i = bid * 2 + half;           // expert slot
        const int r = __ldg(scatter_idx + i);
        if (r < T_TOK) {
            const float factor = __ldg(route_prob_max + r);  // overlaps row loads
            const float4* __restrict__ src4 =
                reinterpret_cast<const float4*>(expert_outputs + (size_t)i * D_DIM);
            float4* __restrict__ dst4 =
                reinterpret_cast<float4*>(out + (size_t)r * D_DIM);

            float4 v0 = __ldcs(&src4[lane]);
            float4 v1 = __ldcs(&src4[lane + 128]);
            float4 v2 = __ldcs(&src4[lane + 256]);
            float4 v3 = __ldcs(&src4[lane + 384]);

            v0.x *= factor; v0.y *= factor; v0.z *= factor; v0.w *= factor;
            v1.x *= factor; v1.y *= factor; v1.z *= factor; v1.w *= factor;
            v2.x *= factor; v2.y *= factor; v2.z *= factor; v2.w *= factor;
            v3.x *= factor; v3.y *= factor; v3.z *= factor; v3.w *= factor;

            __stcs(&dst4[lane],       v0);
            __stcs(&dst4[lane + 128], v1);
            __stcs(&dst4[lane + 256], v2);
            __stcs(&dst4[lane + 384], v3);
        }
    }

    // ---- Fallback section: dropped tokens pass x through (factor 1) ----
    if (bid < T_PAIRS) {
        const int t = bid * 2 + half;
        if (dropped[t]) {
            const float4* __restrict__ src4 =
                reinterpret_cast<const float4*>(x + (size_t)t * D_DIM);
            float4* __restrict__ dst4 =
                reinterpret_cast<float4*>(out + (size_t)t * D_DIM);

            float4 v0 = __ldcs(&src4[lane]);
            float4 v1 = __ldcs(&src4[lane + 128]);
            float4 v2 = __ldcs(&src4[lane + 256]);
            float4 v3 = __ldcs(&src4[lane + 384]);

            __stcs(&dst4[lane],       v0);
            __stcs(&dst4[lane + 128], v1);
            __stcs(&dst4[lane + 256], v2);
            __stcs(&dst4[lane + 384], v3);
        }
    }
}

extern "C" void kernel_launch(void* const* d_in, const int* in_sizes, int n_in,
                              void* d_out, int out_size) {
    const float*         expert_outputs = (const float*)d_in[0];
    const float*         x              = (const float*)d_in[1];
    const float*         route_prob_max = (const float*)d_in[2];
    const int*           scatter_idx    = (const int*)d_in[3];
    const unsigned char* dropped        = (const unsigned char*)d_in[4];
    float* out = (float*)d_out;

    moe_scatter_kernel<<<EC_PAIRS, 256>>>(
        expert_outputs, x, route_prob_max, scatter_idx, dropped, out);
}

// round 11
// speedup vs baseline: 1.0522x; 1.0287x over previous
#include <cuda_runtime.h>
#include <cstdint>

// Problem constants (fixed by the reference):
//   B=4, S=4096, D=2048, E=8, T=B*S=16384, C=T/E*1.25=2560, EC=E*C=20480
#define D_DIM    2048
#define T_TOK    16384
#define EC_ROWS  20480
#define EC_QUADS (EC_ROWS / 4)   // 5120 blocks, 4 expert slots each
#define T_QUADS  (T_TOK / 4)     // first 4096 blocks also cover 4 tokens' fallback

// Single-launch scatter, fat blocks: 512 threads = 4 row-engines of
// 128 lanes x 4 float4 (the measured-best copy shape). Each block handles
// 4 expert slots (skipping padding slots with scatter_idx == T); the first
// T_QUADS blocks also handle the x-fallback for 4 tokens (row copied only
// if dropped). Writer sets are disjoint and cover every output row.
__global__ __launch_bounds__(512) void moe_scatter_kernel(
    const float* __restrict__ expert_outputs,   // [EC, D]
    const float* __restrict__ x,                // [T, D]
    const float* __restrict__ route_prob_max,   // [T]
    const int*   __restrict__ scatter_idx,      // [EC]
    const unsigned char* __restrict__ dropped,  // [T] bool
    float* __restrict__ out)                    // [T, D]
{
    const int tid  = threadIdx.x;
    const int quad = tid >> 7;                  // 0..3: which row of the quad
    const int lane = tid & 127;
    const int bid  = blockIdx.x;

    // ---- Scatter section: expert slot -> token row ----
    {
        const int i = bid * 4 + quad;           // expert slot
        const int r = __ldg(scatter_idx + i);
        if (r < T_TOK) {
            const float factor = __ldg(route_prob_max + r);  // overlaps row loads
            const float4* __restrict__ src4 =
                reinterpret_cast<const float4*>(expert_outputs + (size_t)i * D_DIM);
            float4* __restrict__ dst4 =
                reinterpret_cast<float4*>(out + (size_t)r * D_DIM);

            float4 v0 = __ldcs(&src4[lane]);
            float4 v1 = __ldcs(&src4[lane + 128]);
            float4 v2 = __ldcs(&src4[lane + 256]);
            float4 v3 = __ldcs(&src4[lane + 384]);

            v0.x *= factor; v0.y *= factor; v0.z *= factor; v0.w *= factor;
            v1.x *= factor; v1.y *= factor; v1.z *= factor; v1.w *= factor;
            v2.x *= factor; v2.y *= factor; v2.z *= factor; v2.w *= factor;
            v3.x *= factor; v3.y *= factor; v3.z *= factor; v3.w *= factor;

            __stcs(&dst4[lane],       v0);
            __stcs(&dst4[lane + 128], v1);
            __stcs(&dst4[lane + 256], v2);
            __stcs(&dst4[lane + 384], v3);
        }
    }

    // ---- Fallback section: dropped tokens pass x through (factor 1) ----
    if (bid < T_QUADS) {
        const int t = bid * 4 + quad;
        if (dropped[t]) {
            const float4* __restrict__ src4 =
                reinterpret_cast<const float4*>(x + (size_t)t * D_DIM);
            float4* __restrict__ dst4 =
                reinterpret_cast<float4*>(out + (size_t)t * D_DIM);

            float4 v0 = __ldcs(&src4[lane]);
            float4 v1 = __ldcs(&src4[lane + 128]);
            float4 v2 = __ldcs(&src4[lane + 256]);
            float4 v3 = __ldcs(&src4[lane + 384]);

            __stcs(&dst4[lane],       v0);
            __stcs(&dst4[lane + 128], v1);
            __stcs(&dst4[lane + 256], v2);
            __stcs(&dst4[lane + 384], v3);
        }
    }
}

extern "C" void kernel_launch(void* const* d_in, const int* in_sizes, int n_in,
                              void* d_out, int out_size) {
    const float*         expert_outputs = (const float*)d_in[0];
    const float*         x              = (const float*)d_in[1];
    const float*         route_prob_max = (const float*)d_in[2];
    const int*           scatter_idx    = (const int*)d_in[3];
    const unsigned char* dropped        = (const unsigned char*)d_in[4];
    float* out = (float*)d_out;

    moe_scatter_kernel<<<EC_QUADS, 512>>>(
        expert_outputs, x, route_prob_max, scatter_idx, dropped, out);
}